// round 15
// baseline (speedup 1.0000x reference)
#include <cuda_runtime.h>
#include <cuda_fp16.h>
#include <cstdint>

#define DEV __device__ __forceinline__

constexpr int NB = 8;
constexpr int C  = 64;
constexpr int L  = 4096;
constexpr int BR = 128;           // query rows per CTA (4 warps x 32 rows)
constexpr int BC = 64;            // keys per iteration (2 hp-blocks of 32)
constexpr int NIT = L / BC;       // 64

// fp16 scratch: Q (pre-scaled by log2(e)/64), K, V in [B, L, C] layout
__device__ __half g_Q[NB * L * C];
__device__ __half g_K[NB * L * C];
__device__ __half g_V[NB * L * C];

DEV uint32_t smem_u32(const void* p) { return (uint32_t)__cvta_generic_to_shared(p); }
DEV uint32_t swz(uint32_t o) { return o ^ ((o >> 3) & 0x70); }   // SW128

DEV float fast_rcp(float x) { float r; asm("rcp.approx.ftz.f32 %0, %1;" : "=f"(r) : "f"(x)); return r; }

DEV void cp16(uint32_t dst, const void* src) {
    asm volatile("cp.async.cg.shared.global [%0], [%1], 16;\n" :: "r"(dst), "l"(src));
}
DEV void cp_commit() { asm volatile("cp.async.commit_group;\n"); }
template<int N> DEV void cp_wait() { asm volatile("cp.async.wait_group %0;\n" :: "n"(N)); }

DEV void ldsm_x4(uint32_t& r0, uint32_t& r1, uint32_t& r2, uint32_t& r3, uint32_t a) {
    asm volatile("ldmatrix.sync.aligned.m8n8.x4.shared.b16 {%0,%1,%2,%3}, [%4];"
        : "=r"(r0), "=r"(r1), "=r"(r2), "=r"(r3) : "r"(a));
}
DEV void ldsm_x4t(uint32_t& r0, uint32_t& r1, uint32_t& r2, uint32_t& r3, uint32_t a) {
    asm volatile("ldmatrix.sync.aligned.m8n8.x4.trans.shared.b16 {%0,%1,%2,%3}, [%4];"
        : "=r"(r0), "=r"(r1), "=r"(r2), "=r"(r3) : "r"(a));
}
// f16 inputs, f16 accumulators (2-reg D/C)
DEV void mma_h16(uint32_t& c0, uint32_t& c1,
                 uint32_t a0, uint32_t a1, uint32_t a2, uint32_t a3,
                 uint32_t b0, uint32_t b1) {
    asm volatile("mma.sync.aligned.m16n8k16.row.col.f16.f16.f16.f16 "
        "{%0,%1}, {%2,%3,%4,%5}, {%6,%7}, {%0,%1};"
        : "+r"(c0), "+r"(c1)
        : "r"(a0), "r"(a1), "r"(a2), "r"(a3), "r"(b0), "r"(b1));
}
// f16 inputs, f32 accumulators (projection kernel)
DEV void mma_h16_f32(float& c0, float& c1, float& c2, float& c3,
                     uint32_t a0, uint32_t a1, uint32_t a2, uint32_t a3,
                     uint32_t b0, uint32_t b1) {
    asm volatile("mma.sync.aligned.m16n8k16.row.col.f32.f16.f16.f32 "
        "{%0,%1,%2,%3}, {%4,%5,%6,%7}, {%8,%9}, {%0,%1,%2,%3};"
        : "+f"(c0), "+f"(c1), "+f"(c2), "+f"(c3)
        : "r"(a0), "r"(a1), "r"(a2), "r"(a3), "r"(b0), "r"(b1));
}
DEV uint32_t packh(float lo, float hi) {
    uint32_t r; asm("cvt.rn.f16x2.f32 %0, %1, %2;" : "=r"(r) : "f"(hi), "f"(lo)); return r;
}
DEV uint32_t ex2_h2(uint32_t u) {
    uint32_t r; asm("ex2.approx.f16x2 %0, %1;" : "=r"(r) : "r"(u)); return r;
}
DEV uint32_t hadd2u(uint32_t a, uint32_t b) {
    __half2 r = __hadd2(*(__half2*)&a, *(__half2*)&b);
    return *(uint32_t*)&r;
}
DEV float2 h2_to_f2(uint32_t u) { return __half22float2(*(__half2*)&u); }

// ---------------------------------------------------------------------------
// Kernel A: QKV projection via tensor cores (fp16 in, f32 accum).
// ---------------------------------------------------------------------------
__global__ void __launch_bounds__(256) qkv_kernel(
    const float* __restrict__ x,
    const float* __restrict__ Wq, const float* __restrict__ bq,
    const float* __restrict__ Wk, const float* __restrict__ bk,
    const float* __restrict__ Wv, const float* __restrict__ bv)
{
    __shared__ __align__(16) unsigned char sm[41728];
    const uint32_t wsm = smem_u32(sm);
    const uint32_t xsm = wsm + 24576;
    float* biass = (float*)(sm + 40960);

    const int b    = blockIdx.x >> 5;
    const int tile = blockIdx.x & 31;
    const int l0   = tile * 128;
    const int tid  = threadIdx.x;
    const int lane = tid & 31;
    const int warp = tid >> 5;
    const int wr   = warp * 16;

    for (int idx = tid; idx < 4096; idx += 256) {
        int r = idx >> 6, cc = idx & 63;
        uint32_t so = swz(r * 128 + cc * 2);
        *(__half*)(sm + so)         = __float2half(Wq[idx]);
        *(__half*)(sm + 8192 + so)  = __float2half(Wk[idx]);
        *(__half*)(sm + 16384 + so) = __float2half(Wv[idx]);
    }
    if (tid < 64) {
        biass[tid]       = bq[tid];
        biass[64 + tid]  = bk[tid];
        biass[128 + tid] = bv[tid];
    }
    for (int idx = tid; idx < 8192; idx += 256) {
        int cc = idx >> 7, j = idx & 127;
        float v = x[(size_t)(b * 64 + cc) * 4096 + l0 + j];
        *(__half*)(sm + 24576 + swz(j * 128 + cc * 2)) = __float2half(v);
    }
    __syncthreads();

    uint32_t a[4][4];
    {
        const int m = lane >> 3;
        #pragma unroll
        for (int kt = 0; kt < 4; kt++) {
            int row = wr + (lane & 7) + (m & 1) * 8;
            int ch  = kt * 2 + (m >> 1);
            ldsm_x4(a[kt][0], a[kt][1], a[kt][2], a[kt][3],
                    xsm + swz(row * 128 + ch * 16));
        }
    }

    const int krow = (lane & 7) + ((lane >> 4) & 1) * 8;
    const int kch  = (lane >> 3) & 1;

    float acc[3][8][4];
    #pragma unroll
    for (int m3 = 0; m3 < 3; m3++)
        #pragma unroll
        for (int nt = 0; nt < 8; nt++)
            #pragma unroll
            for (int e = 0; e < 4; e++) acc[m3][nt][e] = 0.f;

    #pragma unroll
    for (int m3 = 0; m3 < 3; m3++) {
        const uint32_t wb = wsm + m3 * 8192;
        #pragma unroll
        for (int kt = 0; kt < 4; kt++) {
            #pragma unroll
            for (int j = 0; j < 4; j++) {
                uint32_t b0, b1, b2, b3;
                int row = j * 16 + krow;
                int ch  = kt * 2 + kch;
                ldsm_x4(b0, b1, b2, b3, wb + swz(row * 128 + ch * 16));
                mma_h16_f32(acc[m3][2*j][0], acc[m3][2*j][1], acc[m3][2*j][2], acc[m3][2*j][3],
                            a[kt][0], a[kt][1], a[kt][2], a[kt][3], b0, b1);
                mma_h16_f32(acc[m3][2*j+1][0], acc[m3][2*j+1][1], acc[m3][2*j+1][2], acc[m3][2*j+1][3],
                            a[kt][0], a[kt][1], a[kt][2], a[kt][3], b2, b3);
            }
        }
    }

    const float fscale = 0.015625f * 1.4426950408889634f;  // (1/64)*log2(e)
    const int r0 = wr + (lane >> 2);
    #pragma unroll
    for (int nt = 0; nt < 8; nt++) {
        int c0 = nt * 8 + (lane & 3) * 2;
        float bQ0 = biass[c0],       bQ1 = biass[c0 + 1];
        float bK0 = biass[64 + c0],  bK1 = biass[64 + c0 + 1];
        float bV0 = biass[128 + c0], bV1 = biass[128 + c0 + 1];
        #pragma unroll
        for (int h = 0; h < 2; h++) {
            size_t go = ((size_t)b * 4096 + l0 + r0 + h * 8) * 64 + c0;
            *(uint32_t*)(g_Q + go) = packh((acc[0][nt][2*h] + bQ0) * fscale,
                                           (acc[0][nt][2*h+1] + bQ1) * fscale);
            *(uint32_t*)(g_K + go) = packh(acc[1][nt][2*h] + bK0,
                                           acc[1][nt][2*h+1] + bK1);
            *(uint32_t*)(g_V + go) = packh(acc[2][nt][2*h] + bV0,
                                           acc[2][nt][2*h+1] + bV1);
        }
    }
}

// ---------------------------------------------------------------------------
// Kernel B: FlashAttention fp16 — R11 verbatim except __launch_bounds__(128,3):
// caps regs at 170 (architectural need ~100, no spills expected) -> 3 CTAs/SM
// = 12 warps/SM in 3 independent barrier domains covering each other's
// softmax/ldsm bubbles.
// out[b,c,l] = gamma * (softmax(Q K^T / 64) V)[l,c] + x[b,c,l]
// ---------------------------------------------------------------------------
// dynamic smem (65536 B):
//  main:     Q [128][128B] @0 (16KB) | K 3x8KB @16384 | V 3x8KB @40960
//  epilogue: Os [64][132] f32 @0 (33792 B) overlay
__global__ void __launch_bounds__(128, 3) attn_kernel(
    const float* __restrict__ x,
    const float* __restrict__ gamma,
    float* __restrict__ out)
{
    extern __shared__ __align__(16) unsigned char smem[];
    const int b    = blockIdx.x >> 5;
    const int q0   = (blockIdx.x & 31) * BR;
    const int tid  = threadIdx.x;
    const int lane = tid & 31;
    const int warp = tid >> 5;
    const int wr   = warp * 32;

    const uint32_t qs = smem_u32(smem);
    const uint32_t ks = qs + 16384;
    const uint32_t vs = qs + 40960;

    const __half* Qg = g_Q + ((size_t)b * L + q0) * C;
    const __half* Kg = g_K + (size_t)b * L * C;
    const __half* Vg = g_V + (size_t)b * L * C;

    // Prologue: group0 = Q + stage0, group1 = stage1
    for (int i = tid; i < 1024; i += 128) {
        int r = i >> 3, ck = i & 7;
        cp16(qs + swz(r * 128 + ck * 16), (const char*)Qg + r * 128 + ck * 16);
    }
    for (int i = tid; i < 512; i += 128) {
        int r = i >> 3, ck = i & 7;
        uint32_t so = swz(r * 128 + ck * 16);
        cp16(ks + so, (const char*)Kg + r * 128 + ck * 16);
        cp16(vs + so, (const char*)Vg + r * 128 + ck * 16);
    }
    cp_commit();
    {
        const char* K1 = (const char*)(Kg + (size_t)BC * C);
        const char* V1 = (const char*)(Vg + (size_t)BC * C);
        for (int i = tid; i < 512; i += 128) {
            int r = i >> 3, ck = i & 7;
            uint32_t so = swz(r * 128 + ck * 16);
            cp16(ks + 8192 + so, K1 + r * 128 + ck * 16);
            cp16(vs + 8192 + so, V1 + r * 128 + ck * 16);
        }
        cp_commit();
    }
    cp_wait<1>();          // Q + stage0 complete
    __syncthreads();

    // Q fragments: [mtile 0..1][ktile 0..3][4 regs]
    uint32_t qa[2][4][4];
    {
        const int m = lane >> 3;
        #pragma unroll
        for (int mt = 0; mt < 2; mt++)
            #pragma unroll
            for (int kt = 0; kt < 4; kt++) {
                int row = wr + mt * 16 + (lane & 7) + (m & 1) * 8;
                int ch  = kt * 2 + (m >> 1);
                ldsm_x4(qa[mt][kt][0], qa[mt][kt][1], qa[mt][kt][2], qa[mt][kt][3],
                        qs + swz(row * 128 + ch * 16));
            }
    }

    float lpart[4] = {0.f, 0.f, 0.f, 0.f};
    uint32_t o[2][8][2];   // f16x2 accumulators
    #pragma unroll
    for (int mt = 0; mt < 2; mt++)
        #pragma unroll
        for (int ct = 0; ct < 8; ct++) { o[mt][ct][0] = 0u; o[mt][ct][1] = 0u; }

    // Per-lane invariant address components
    const int krow = (lane & 7) + ((lane >> 4) & 1) * 8;   // + hp*32 + j*16
    const int kch  = (lane >> 3) & 1;                      // + kt*2
    const int vrow = (lane & 7) + ((lane >> 3) & 1) * 8;   // + hp*32 + kk*16
    const int vcb  = ((lane >> 4) & 1) * 16;               // + j*32 (bytes)

    for (int it = 0; it < NIT; it++) {
        // Prefetch stage it+2 into buffer (it+2)%3
        if (it + 2 < NIT) {
            int nb = (it + 2) % 3;
            const char* Kn = (const char*)(Kg + (size_t)(it + 2) * BC * C);
            const char* Vn = (const char*)(Vg + (size_t)(it + 2) * BC * C);
            for (int i = tid; i < 512; i += 128) {
                int r = i >> 3, ck = i & 7;
                uint32_t so = swz(r * 128 + ck * 16);
                cp16(ks + nb * 8192 + so, Kn + r * 128 + ck * 16);
                cp16(vs + nb * 8192 + so, Vn + r * 128 + ck * 16);
            }
            cp_commit();
        }

        const uint32_t kbase = ks + (it % 3) * 8192;
        const uint32_t vbase = vs + (it % 3) * 8192;

        // Two passes over 32-key halves
        #pragma unroll
        for (int hp = 0; hp < 2; hp++) {
            // S = Q K^T over 32 keys, f16 accumulate
            uint32_t s[2][4][2];
            #pragma unroll
            for (int mt = 0; mt < 2; mt++)
                #pragma unroll
                for (int nt = 0; nt < 4; nt++) { s[mt][nt][0] = 0u; s[mt][nt][1] = 0u; }

            #pragma unroll
            for (int kt = 0; kt < 4; kt++) {
                #pragma unroll
                for (int j = 0; j < 2; j++) {
                    uint32_t b0, b1, b2, b3;
                    int row = hp * 32 + j * 16 + krow;
                    int ch  = kt * 2 + kch;
                    ldsm_x4(b0, b1, b2, b3, kbase + swz(row * 128 + ch * 16));
                    #pragma unroll
                    for (int mt = 0; mt < 2; mt++) {
                        mma_h16(s[mt][2*j][0], s[mt][2*j][1],
                                qa[mt][kt][0], qa[mt][kt][1], qa[mt][kt][2], qa[mt][kt][3],
                                b0, b1);
                        mma_h16(s[mt][2*j+1][0], s[mt][2*j+1][1],
                                qa[mt][kt][0], qa[mt][kt][1], qa[mt][kt][2], qa[mt][kt][3],
                                b2, b3);
                    }
                }
            }

            // P = exp2(S) — S accumulator regs ARE the A-fragment layout.
            uint32_t pf[2][4][2];
            #pragma unroll
            for (int mt = 0; mt < 2; mt++) {
                uint32_t l2a = 0u, l2b = 0u;
                #pragma unroll
                for (int nt = 0; nt < 4; nt++) {
                    uint32_t u0 = ex2_h2(s[mt][nt][0]);
                    uint32_t u1 = ex2_h2(s[mt][nt][1]);
                    pf[mt][nt][0] = u0; pf[mt][nt][1] = u1;
                    l2a = hadd2u(l2a, u0);
                    l2b = hadd2u(l2b, u1);
                }
                float2 fa = h2_to_f2(l2a), fb = h2_to_f2(l2b);
                lpart[mt * 2]     += fa.x + fa.y;
                lpart[mt * 2 + 1] += fb.x + fb.y;
            }

            // O += P V over these 32 keys (all 64 channels), f16 accumulate
            #pragma unroll
            for (int kk = 0; kk < 2; kk++) {
                #pragma unroll
                for (int j = 0; j < 4; j++) {
                    uint32_t v0, v1, v2, v3;
                    int row = hp * 32 + kk * 16 + vrow;
                    ldsm_x4t(v0, v1, v2, v3, vbase + swz(row * 128 + j * 32 + vcb));
                    #pragma unroll
                    for (int mt = 0; mt < 2; mt++) {
                        mma_h16(o[mt][2*j][0], o[mt][2*j][1],
                                pf[mt][2*kk][0], pf[mt][2*kk][1],
                                pf[mt][2*kk+1][0], pf[mt][2*kk+1][1], v0, v1);
                        mma_h16(o[mt][2*j+1][0], o[mt][2*j+1][1],
                                pf[mt][2*kk][0], pf[mt][2*kk][1],
                                pf[mt][2*kk+1][0], pf[mt][2*kk+1][1], v2, v3);
                    }
                }
            }
        }

        if (it + 1 < NIT) {
            if (it + 2 < NIT) cp_wait<1>(); else cp_wait<0>();
            __syncthreads();
        }
    }

    // Row-sum reduction within quads (columns of a row live across lanes ^1,^2)
    #pragma unroll
    for (int h = 0; h < 4; h++) {
        lpart[h] += __shfl_xor_sync(0xffffffffu, lpart[h], 1);
        lpart[h] += __shfl_xor_sync(0xffffffffu, lpart[h], 2);
    }
    float inv[4];
    #pragma unroll
    for (int h = 0; h < 4; h++) inv[h] = fast_rcp(lpart[h]);

    // Epilogue: normalize, transpose through smem, fused residual write
    __syncthreads();
    float* Os = (float*)smem;   // [64][132]

    #pragma unroll
    for (int mt = 0; mt < 2; mt++)
        #pragma unroll
        for (int h = 0; h < 2; h++) {
            int row  = wr + mt * 16 + h * 8 + (lane >> 2);
            float iv = inv[mt * 2 + h];
            #pragma unroll
            for (int ct = 0; ct < 8; ct++) {
                int c0 = ct * 8 + 2 * (lane & 3);
                float2 f = h2_to_f2(o[mt][ct][h]);
                Os[c0 * 132 + row]       = f.x * iv;
                Os[(c0 + 1) * 132 + row] = f.y * iv;
            }
        }
    __syncthreads();

    const float gam = gamma[0];
    for (int idx = tid; idx < 64 * 128; idx += 128) {
        int c = idx >> 7, j = idx & 127;
        size_t gi = ((size_t)(b * 64 + c)) * 4096 + q0 + j;
        out[gi] = gam * Os[c * 132 + j] + x[gi];
    }
}

// ---------------------------------------------------------------------------
extern "C" void kernel_launch(void* const* d_in, const int* in_sizes, int n_in,
                              void* d_out, int out_size) {
    (void)in_sizes; (void)n_in; (void)out_size;
    const float* x     = (const float*)d_in[0];
    const float* Wq    = (const float*)d_in[1];
    const float* bq    = (const float*)d_in[2];
    const float* Wk    = (const float*)d_in[3];
    const float* bk    = (const float*)d_in[4];
    const float* Wv    = (const float*)d_in[5];
    const float* bv    = (const float*)d_in[6];
    const float* gamma = (const float*)d_in[7];
    float* out = (float*)d_out;

    cudaFuncSetAttribute(attn_kernel, cudaFuncAttributeMaxDynamicSharedMemorySize, 65536);

    qkv_kernel<<<NB * 32, 256>>>(x, Wq, bq, Wk, bk, Wv, bv);
    attn_kernel<<<NB * (L / BR), 128, 65536>>>(x, gamma, out);
}

// round 16
// speedup vs baseline: 1.0143x; 1.0143x over previous
#include <cuda_runtime.h>
#include <cuda_fp16.h>
#include <cstdint>

#define DEV __device__ __forceinline__

constexpr int NB = 8;
constexpr int C  = 64;
constexpr int L  = 4096;
constexpr int BR = 128;           // query rows per CTA (4 warps x 32 rows)
constexpr int BC = 128;           // keys per iteration (4 hp-blocks of 32)
constexpr int NIT = L / BC;       // 32

// fp16 scratch: Q (pre-scaled by log2(e)/64), K, V in [B, L, C] layout
__device__ __half g_Q[NB * L * C];
__device__ __half g_K[NB * L * C];
__device__ __half g_V[NB * L * C];

DEV uint32_t smem_u32(const void* p) { return (uint32_t)__cvta_generic_to_shared(p); }
DEV uint32_t swz(uint32_t o) { return o ^ ((o >> 3) & 0x70); }   // SW128

DEV float fast_rcp(float x) { float r; asm("rcp.approx.ftz.f32 %0, %1;" : "=f"(r) : "f"(x)); return r; }

DEV void cp16(uint32_t dst, const void* src) {
    asm volatile("cp.async.cg.shared.global [%0], [%1], 16;\n" :: "r"(dst), "l"(src));
}
DEV void cp_commit() { asm volatile("cp.async.commit_group;\n"); }
template<int N> DEV void cp_wait() { asm volatile("cp.async.wait_group %0;\n" :: "n"(N)); }

DEV void ldsm_x4(uint32_t& r0, uint32_t& r1, uint32_t& r2, uint32_t& r3, uint32_t a) {
    asm volatile("ldmatrix.sync.aligned.m8n8.x4.shared.b16 {%0,%1,%2,%3}, [%4];"
        : "=r"(r0), "=r"(r1), "=r"(r2), "=r"(r3) : "r"(a));
}
DEV void ldsm_x4t(uint32_t& r0, uint32_t& r1, uint32_t& r2, uint32_t& r3, uint32_t a) {
    asm volatile("ldmatrix.sync.aligned.m8n8.x4.trans.shared.b16 {%0,%1,%2,%3}, [%4];"
        : "=r"(r0), "=r"(r1), "=r"(r2), "=r"(r3) : "r"(a));
}
// f16 inputs, f16 accumulators (2-reg D/C)
DEV void mma_h16(uint32_t& c0, uint32_t& c1,
                 uint32_t a0, uint32_t a1, uint32_t a2, uint32_t a3,
                 uint32_t b0, uint32_t b1) {
    asm volatile("mma.sync.aligned.m16n8k16.row.col.f16.f16.f16.f16 "
        "{%0,%1}, {%2,%3,%4,%5}, {%6,%7}, {%0,%1};"
        : "+r"(c0), "+r"(c1)
        : "r"(a0), "r"(a1), "r"(a2), "r"(a3), "r"(b0), "r"(b1));
}
// f16 inputs, f32 accumulators (projection kernel)
DEV void mma_h16_f32(float& c0, float& c1, float& c2, float& c3,
                     uint32_t a0, uint32_t a1, uint32_t a2, uint32_t a3,
                     uint32_t b0, uint32_t b1) {
    asm volatile("mma.sync.aligned.m16n8k16.row.col.f32.f16.f16.f32 "
        "{%0,%1,%2,%3}, {%4,%5,%6,%7}, {%8,%9}, {%0,%1,%2,%3};"
        : "+f"(c0), "+f"(c1), "+f"(c2), "+f"(c3)
        : "r"(a0), "r"(a1), "r"(a2), "r"(a3), "r"(b0), "r"(b1));
}
DEV uint32_t packh(float lo, float hi) {
    uint32_t r; asm("cvt.rn.f16x2.f32 %0, %1, %2;" : "=r"(r) : "f"(hi), "f"(lo)); return r;
}
DEV uint32_t ex2_h2(uint32_t u) {
    uint32_t r; asm("ex2.approx.f16x2 %0, %1;" : "=r"(r) : "r"(u)); return r;
}
DEV uint32_t hadd2u(uint32_t a, uint32_t b) {
    __half2 r = __hadd2(*(__half2*)&a, *(__half2*)&b);
    return *(uint32_t*)&r;
}
DEV float2 h2_to_f2(uint32_t u) { return __half22float2(*(__half2*)&u); }

// ---------------------------------------------------------------------------
// Kernel A: QKV projection via tensor cores (fp16 in, f32 accum).
// ---------------------------------------------------------------------------
__global__ void __launch_bounds__(256) qkv_kernel(
    const float* __restrict__ x,
    const float* __restrict__ Wq, const float* __restrict__ bq,
    const float* __restrict__ Wk, const float* __restrict__ bk,
    const float* __restrict__ Wv, const float* __restrict__ bv)
{
    __shared__ __align__(16) unsigned char sm[41728];
    const uint32_t wsm = smem_u32(sm);
    const uint32_t xsm = wsm + 24576;
    float* biass = (float*)(sm + 40960);

    const int b    = blockIdx.x >> 5;
    const int tile = blockIdx.x & 31;
    const int l0   = tile * 128;
    const int tid  = threadIdx.x;
    const int lane = tid & 31;
    const int warp = tid >> 5;
    const int wr   = warp * 16;

    for (int idx = tid; idx < 4096; idx += 256) {
        int r = idx >> 6, cc = idx & 63;
        uint32_t so = swz(r * 128 + cc * 2);
        *(__half*)(sm + so)         = __float2half(Wq[idx]);
        *(__half*)(sm + 8192 + so)  = __float2half(Wk[idx]);
        *(__half*)(sm + 16384 + so) = __float2half(Wv[idx]);
    }
    if (tid < 64) {
        biass[tid]       = bq[tid];
        biass[64 + tid]  = bk[tid];
        biass[128 + tid] = bv[tid];
    }
    for (int idx = tid; idx < 8192; idx += 256) {
        int cc = idx >> 7, j = idx & 127;
        float v = x[(size_t)(b * 64 + cc) * 4096 + l0 + j];
        *(__half*)(sm + 24576 + swz(j * 128 + cc * 2)) = __float2half(v);
    }
    __syncthreads();

    uint32_t a[4][4];
    {
        const int m = lane >> 3;
        #pragma unroll
        for (int kt = 0; kt < 4; kt++) {
            int row = wr + (lane & 7) + (m & 1) * 8;
            int ch  = kt * 2 + (m >> 1);
            ldsm_x4(a[kt][0], a[kt][1], a[kt][2], a[kt][3],
                    xsm + swz(row * 128 + ch * 16));
        }
    }

    const int krow = (lane & 7) + ((lane >> 4) & 1) * 8;
    const int kch  = (lane >> 3) & 1;

    float acc[3][8][4];
    #pragma unroll
    for (int m3 = 0; m3 < 3; m3++)
        #pragma unroll
        for (int nt = 0; nt < 8; nt++)
            #pragma unroll
            for (int e = 0; e < 4; e++) acc[m3][nt][e] = 0.f;

    #pragma unroll
    for (int m3 = 0; m3 < 3; m3++) {
        const uint32_t wb = wsm + m3 * 8192;
        #pragma unroll
        for (int kt = 0; kt < 4; kt++) {
            #pragma unroll
            for (int j = 0; j < 4; j++) {
                uint32_t b0, b1, b2, b3;
                int row = j * 16 + krow;
                int ch  = kt * 2 + kch;
                ldsm_x4(b0, b1, b2, b3, wb + swz(row * 128 + ch * 16));
                mma_h16_f32(acc[m3][2*j][0], acc[m3][2*j][1], acc[m3][2*j][2], acc[m3][2*j][3],
                            a[kt][0], a[kt][1], a[kt][2], a[kt][3], b0, b1);
                mma_h16_f32(acc[m3][2*j+1][0], acc[m3][2*j+1][1], acc[m3][2*j+1][2], acc[m3][2*j+1][3],
                            a[kt][0], a[kt][1], a[kt][2], a[kt][3], b2, b3);
            }
        }
    }

    const float fscale = 0.015625f * 1.4426950408889634f;  // (1/64)*log2(e)
    const int r0 = wr + (lane >> 2);
    #pragma unroll
    for (int nt = 0; nt < 8; nt++) {
        int c0 = nt * 8 + (lane & 3) * 2;
        float bQ0 = biass[c0],       bQ1 = biass[c0 + 1];
        float bK0 = biass[64 + c0],  bK1 = biass[64 + c0 + 1];
        float bV0 = biass[128 + c0], bV1 = biass[128 + c0 + 1];
        #pragma unroll
        for (int h = 0; h < 2; h++) {
            size_t go = ((size_t)b * 4096 + l0 + r0 + h * 8) * 64 + c0;
            *(uint32_t*)(g_Q + go) = packh((acc[0][nt][2*h] + bQ0) * fscale,
                                           (acc[0][nt][2*h+1] + bQ1) * fscale);
            *(uint32_t*)(g_K + go) = packh(acc[1][nt][2*h] + bK0,
                                           acc[1][nt][2*h+1] + bK1);
            *(uint32_t*)(g_V + go) = packh(acc[2][nt][2*h] + bV0,
                                           acc[2][nt][2*h+1] + bV1);
        }
    }
}

// ---------------------------------------------------------------------------
// Kernel B: FlashAttention fp16 — R11 inner structure verbatim, but BC=128:
// 4 hp-blocks of 32 keys per iteration, 2-stage 16KB K/V ring. Barriers and
// cp_wait convoys halved (64 -> 32). fp16 score buffers keep regs well under
// the 255 cliff that killed the bf16 BC=128 attempt.
// out[b,c,l] = gamma * (softmax(Q K^T / 64) V)[l,c] + x[b,c,l]
// ---------------------------------------------------------------------------
// dynamic smem (81920 B):
//  main:     Q [128][128B] @0 (16KB) | K 2x16KB @16384 | V 2x16KB @49152
//  epilogue: Os [64][132] f32 @0 (33792 B) overlay
__global__ void __launch_bounds__(128, 2) attn_kernel(
    const float* __restrict__ x,
    const float* __restrict__ gamma,
    float* __restrict__ out)
{
    extern __shared__ __align__(16) unsigned char smem[];
    const int b    = blockIdx.x >> 5;
    const int q0   = (blockIdx.x & 31) * BR;
    const int tid  = threadIdx.x;
    const int lane = tid & 31;
    const int warp = tid >> 5;
    const int wr   = warp * 32;

    const uint32_t qs = smem_u32(smem);
    const uint32_t ks = qs + 16384;
    const uint32_t vs = qs + 49152;

    const __half* Qg = g_Q + ((size_t)b * L + q0) * C;
    const __half* Kg = g_K + (size_t)b * L * C;
    const __half* Vg = g_V + (size_t)b * L * C;

    // Prologue: group0 = Q + K0 + V0, group1 = K1 + V1
    for (int i = tid; i < 1024; i += 128) {
        int r = i >> 3, ck = i & 7;
        uint32_t so = swz(r * 128 + ck * 16);
        cp16(qs + so, (const char*)Qg + r * 128 + ck * 16);
        cp16(ks + so, (const char*)Kg + r * 128 + ck * 16);
        cp16(vs + so, (const char*)Vg + r * 128 + ck * 16);
    }
    cp_commit();
    {
        const char* K1 = (const char*)(Kg + (size_t)BC * C);
        const char* V1 = (const char*)(Vg + (size_t)BC * C);
        for (int i = tid; i < 1024; i += 128) {
            int r = i >> 3, ck = i & 7;
            uint32_t so = swz(r * 128 + ck * 16);
            cp16(ks + 16384 + so, K1 + r * 128 + ck * 16);
            cp16(vs + 16384 + so, V1 + r * 128 + ck * 16);
        }
        cp_commit();
    }
    cp_wait<1>();          // Q + stage0 complete
    __syncthreads();

    // Q fragments: [mtile 0..1][ktile 0..3][4 regs]
    uint32_t qa[2][4][4];
    {
        const int m = lane >> 3;
        #pragma unroll
        for (int mt = 0; mt < 2; mt++)
            #pragma unroll
            for (int kt = 0; kt < 4; kt++) {
                int row = wr + mt * 16 + (lane & 7) + (m & 1) * 8;
                int ch  = kt * 2 + (m >> 1);
                ldsm_x4(qa[mt][kt][0], qa[mt][kt][1], qa[mt][kt][2], qa[mt][kt][3],
                        qs + swz(row * 128 + ch * 16));
            }
    }

    float lpart[4] = {0.f, 0.f, 0.f, 0.f};
    uint32_t o[2][8][2];   // f16x2 accumulators
    #pragma unroll
    for (int mt = 0; mt < 2; mt++)
        #pragma unroll
        for (int ct = 0; ct < 8; ct++) { o[mt][ct][0] = 0u; o[mt][ct][1] = 0u; }

    // Per-lane invariant address components
    const int krow = (lane & 7) + ((lane >> 4) & 1) * 8;   // + hp*32 + j*16
    const int kch  = (lane >> 3) & 1;                      // + kt*2
    const int vrow = (lane & 7) + ((lane >> 3) & 1) * 8;   // + hp*32 + kk*16
    const int vcb  = ((lane >> 4) & 1) * 16;               // + j*32 (bytes)

    for (int it = 0; it < NIT; it++) {
        // Prefetch tile it+1 into the other 16KB stage (freed by the barrier
        // at the end of iteration it-1).
        if (it + 1 < NIT) {
            int nb = (it + 1) & 1;
            const char* Kn = (const char*)(Kg + (size_t)(it + 1) * BC * C);
            const char* Vn = (const char*)(Vg + (size_t)(it + 1) * BC * C);
            for (int i = tid; i < 1024; i += 128) {
                int r = i >> 3, ck = i & 7;
                uint32_t so = swz(r * 128 + ck * 16);
                cp16(ks + nb * 16384 + so, Kn + r * 128 + ck * 16);
                cp16(vs + nb * 16384 + so, Vn + r * 128 + ck * 16);
            }
            cp_commit();
        }

        const uint32_t kbase = ks + (it & 1) * 16384;
        const uint32_t vbase = vs + (it & 1) * 16384;

        // Four passes over 32-key blocks (R11 ordering inside each block)
        #pragma unroll
        for (int hp = 0; hp < 4; hp++) {
            // S = Q K^T over 32 keys, f16 accumulate
            uint32_t s[2][4][2];
            #pragma unroll
            for (int mt = 0; mt < 2; mt++)
                #pragma unroll
                for (int nt = 0; nt < 4; nt++) { s[mt][nt][0] = 0u; s[mt][nt][1] = 0u; }

            #pragma unroll
            for (int kt = 0; kt < 4; kt++) {
                #pragma unroll
                for (int j = 0; j < 2; j++) {
                    uint32_t b0, b1, b2, b3;
                    int row = hp * 32 + j * 16 + krow;
                    int ch  = kt * 2 + kch;
                    ldsm_x4(b0, b1, b2, b3, kbase + swz(row * 128 + ch * 16));
                    #pragma unroll
                    for (int mt = 0; mt < 2; mt++) {
                        mma_h16(s[mt][2*j][0], s[mt][2*j][1],
                                qa[mt][kt][0], qa[mt][kt][1], qa[mt][kt][2], qa[mt][kt][3],
                                b0, b1);
                        mma_h16(s[mt][2*j+1][0], s[mt][2*j+1][1],
                                qa[mt][kt][0], qa[mt][kt][1], qa[mt][kt][2], qa[mt][kt][3],
                                b2, b3);
                    }
                }
            }

            // P = exp2(S) — S accumulator regs ARE the A-fragment layout.
            uint32_t pf[2][4][2];
            #pragma unroll
            for (int mt = 0; mt < 2; mt++) {
                uint32_t l2a = 0u, l2b = 0u;
                #pragma unroll
                for (int nt = 0; nt < 4; nt++) {
                    uint32_t u0 = ex2_h2(s[mt][nt][0]);
                    uint32_t u1 = ex2_h2(s[mt][nt][1]);
                    pf[mt][nt][0] = u0; pf[mt][nt][1] = u1;
                    l2a = hadd2u(l2a, u0);
                    l2b = hadd2u(l2b, u1);
                }
                float2 fa = h2_to_f2(l2a), fb = h2_to_f2(l2b);
                lpart[mt * 2]     += fa.x + fa.y;
                lpart[mt * 2 + 1] += fb.x + fb.y;
            }

            // O += P V over these 32 keys (all 64 channels), f16 accumulate
            #pragma unroll
            for (int kk = 0; kk < 2; kk++) {
                #pragma unroll
                for (int j = 0; j < 4; j++) {
                    uint32_t v0, v1, v2, v3;
                    int row = hp * 32 + kk * 16 + vrow;
                    ldsm_x4t(v0, v1, v2, v3, vbase + swz(row * 128 + j * 32 + vcb));
                    #pragma unroll
                    for (int mt = 0; mt < 2; mt++) {
                        mma_h16(o[mt][2*j][0], o[mt][2*j][1],
                                pf[mt][2*kk][0], pf[mt][2*kk][1],
                                pf[mt][2*kk+1][0], pf[mt][2*kk+1][1], v0, v1);
                        mma_h16(o[mt][2*j+1][0], o[mt][2*j+1][1],
                                pf[mt][2*kk][0], pf[mt][2*kk][1],
                                pf[mt][2*kk+1][0], pf[mt][2*kk+1][1], v2, v3);
                    }
                }
            }
        }

        if (it + 1 < NIT) {
            cp_wait<0>();      // next stage resident (had a full iteration)
            __syncthreads();
        }
    }

    // Row-sum reduction within quads (columns of a row live across lanes ^1,^2)
    #pragma unroll
    for (int h = 0; h < 4; h++) {
        lpart[h] += __shfl_xor_sync(0xffffffffu, lpart[h], 1);
        lpart[h] += __shfl_xor_sync(0xffffffffu, lpart[h], 2);
    }
    float inv[4];
    #pragma unroll
    for (int h = 0; h < 4; h++) inv[h] = fast_rcp(lpart[h]);

    // Epilogue: normalize, transpose through smem, fused residual write
    __syncthreads();
    float* Os = (float*)smem;   // [64][132]

    #pragma unroll
    for (int mt = 0; mt < 2; mt++)
        #pragma unroll
        for (int h = 0; h < 2; h++) {
            int row  = wr + mt * 16 + h * 8 + (lane >> 2);
            float iv = inv[mt * 2 + h];
            #pragma unroll
            for (int ct = 0; ct < 8; ct++) {
                int c0 = ct * 8 + 2 * (lane & 3);
                float2 f = h2_to_f2(o[mt][ct][h]);
                Os[c0 * 132 + row]       = f.x * iv;
                Os[(c0 + 1) * 132 + row] = f.y * iv;
            }
        }
    __syncthreads();

    const float gam = gamma[0];
    for (int idx = tid; idx < 64 * 128; idx += 128) {
        int c = idx >> 7, j = idx & 127;
        size_t gi = ((size_t)(b * 64 + c)) * 4096 + q0 + j;
        out[gi] = gam * Os[c * 132 + j] + x[gi];
    }
}

// ---------------------------------------------------------------------------
extern "C" void kernel_launch(void* const* d_in, const int* in_sizes, int n_in,
                              void* d_out, int out_size) {
    (void)in_sizes; (void)n_in; (void)out_size;
    const float* x     = (const float*)d_in[0];
    const float* Wq    = (const float*)d_in[1];
    const float* bq    = (const float*)d_in[2];
    const float* Wk    = (const float*)d_in[3];
    const float* bk    = (const float*)d_in[4];
    const float* Wv    = (const float*)d_in[5];
    const float* bv    = (const float*)d_in[6];
    const float* gamma = (const float*)d_in[7];
    float* out = (float*)d_out;

    cudaFuncSetAttribute(attn_kernel, cudaFuncAttributeMaxDynamicSharedMemorySize, 81920);

    qkv_kernel<<<NB * 32, 256>>>(x, Wq, bq, Wk, bk, Wv, bv);
    attn_kernel<<<NB * (L / BR), 128, 81920>>>(x, gamma, out);
}

// round 17
// speedup vs baseline: 1.1478x; 1.1316x over previous
#include <cuda_runtime.h>
#include <cuda_fp16.h>
#include <cstdint>

#define DEV __device__ __forceinline__

constexpr int NB = 8;
constexpr int C  = 64;
constexpr int L  = 4096;
constexpr int BR = 128;           // query rows per CTA (4 warps x 32 rows)
constexpr int BC = 64;            // keys per iteration (2 passes of 32)
constexpr int NIT = L / BC;       // 64

// fp16 scratch: Q (pre-scaled by log2(e)/64), K, V in [B, L, C] layout
__device__ __half g_Q[NB * L * C];
__device__ __half g_K[NB * L * C];
__device__ __half g_V[NB * L * C];

DEV uint32_t smem_u32(const void* p) { return (uint32_t)__cvta_generic_to_shared(p); }
DEV uint32_t swz(uint32_t o) { return o ^ ((o >> 3) & 0x70); }   // SW128

DEV float fast_rcp(float x) { float r; asm("rcp.approx.ftz.f32 %0, %1;" : "=f"(r) : "f"(x)); return r; }

DEV void cp16(uint32_t dst, const void* src) {
    asm volatile("cp.async.cg.shared.global [%0], [%1], 16;\n" :: "r"(dst), "l"(src));
}
DEV void cp_commit() { asm volatile("cp.async.commit_group;\n"); }
template<int N> DEV void cp_wait() { asm volatile("cp.async.wait_group %0;\n" :: "n"(N)); }

DEV void ldsm_x4(uint32_t& r0, uint32_t& r1, uint32_t& r2, uint32_t& r3, uint32_t a) {
    asm volatile("ldmatrix.sync.aligned.m8n8.x4.shared.b16 {%0,%1,%2,%3}, [%4];"
        : "=r"(r0), "=r"(r1), "=r"(r2), "=r"(r3) : "r"(a));
}
DEV void ldsm_x4t(uint32_t& r0, uint32_t& r1, uint32_t& r2, uint32_t& r3, uint32_t a) {
    asm volatile("ldmatrix.sync.aligned.m8n8.x4.trans.shared.b16 {%0,%1,%2,%3}, [%4];"
        : "=r"(r0), "=r"(r1), "=r"(r2), "=r"(r3) : "r"(a));
}
// f16 inputs, f16 accumulators (2-reg D/C) — the double-rate legacy path
DEV void mma_h16(uint32_t& c0, uint32_t& c1,
                 uint32_t a0, uint32_t a1, uint32_t a2, uint32_t a3,
                 uint32_t b0, uint32_t b1) {
    asm volatile("mma.sync.aligned.m16n8k16.row.col.f16.f16.f16.f16 "
        "{%0,%1}, {%2,%3,%4,%5}, {%6,%7}, {%0,%1};"
        : "+r"(c0), "+r"(c1)
        : "r"(a0), "r"(a1), "r"(a2), "r"(a3), "r"(b0), "r"(b1));
}
// f16 inputs, f32 accumulators (projection kernel: accuracy, cost irrelevant)
DEV void mma_h16_f32(float& c0, float& c1, float& c2, float& c3,
                     uint32_t a0, uint32_t a1, uint32_t a2, uint32_t a3,
                     uint32_t b0, uint32_t b1) {
    asm volatile("mma.sync.aligned.m16n8k16.row.col.f32.f16.f16.f32 "
        "{%0,%1,%2,%3}, {%4,%5,%6,%7}, {%8,%9}, {%0,%1,%2,%3};"
        : "+f"(c0), "+f"(c1), "+f"(c2), "+f"(c3)
        : "r"(a0), "r"(a1), "r"(a2), "r"(a3), "r"(b0), "r"(b1));
}
DEV uint32_t packh(float lo, float hi) {
    uint32_t r; asm("cvt.rn.f16x2.f32 %0, %1, %2;" : "=r"(r) : "f"(hi), "f"(lo)); return r;
}
DEV uint32_t ex2_h2(uint32_t u) {
    uint32_t r; asm("ex2.approx.f16x2 %0, %1;" : "=r"(r) : "r"(u)); return r;
}
DEV uint32_t hadd2u(uint32_t a, uint32_t b) {
    __half2 r = __hadd2(*(__half2*)&a, *(__half2*)&b);
    return *(uint32_t*)&r;
}
DEV float2 h2_to_f2(uint32_t u) { return __half22float2(*(__half2*)&u); }

// ---------------------------------------------------------------------------
// Kernel A: QKV projection via tensor cores (fp16 in, f32 accum).
// x:[B,C,L] f32 -> (fp16 via smem transpose) A[l,c]; W[out,in] as B-operand.
// Q pre-scaled by (1/64)*log2(e).  256 thr, 8 warps x 16 rows, 128 L per CTA.
// ---------------------------------------------------------------------------
__global__ void __launch_bounds__(256) qkv_kernel(
    const float* __restrict__ x,
    const float* __restrict__ Wq, const float* __restrict__ bq,
    const float* __restrict__ Wk, const float* __restrict__ bk,
    const float* __restrict__ Wv, const float* __restrict__ bv)
{
    __shared__ __align__(16) unsigned char sm[41728];
    // [0, 24576): W f16 [3][64][64] swizzled (8KB each)
    // [24576, 40960): X f16 [128 l][64 c] swizzled (16KB)
    // [40960, 41728): bias f32 [3][64]
    const uint32_t wsm = smem_u32(sm);
    const uint32_t xsm = wsm + 24576;
    float* biass = (float*)(sm + 40960);

    const int b    = blockIdx.x >> 5;
    const int tile = blockIdx.x & 31;
    const int l0   = tile * 128;
    const int tid  = threadIdx.x;
    const int lane = tid & 31;
    const int warp = tid >> 5;
    const int wr   = warp * 16;

    for (int idx = tid; idx < 4096; idx += 256) {
        int r = idx >> 6, cc = idx & 63;
        uint32_t so = swz(r * 128 + cc * 2);
        *(__half*)(sm + so)         = __float2half(Wq[idx]);
        *(__half*)(sm + 8192 + so)  = __float2half(Wk[idx]);
        *(__half*)(sm + 16384 + so) = __float2half(Wv[idx]);
    }
    if (tid < 64) {
        biass[tid]       = bq[tid];
        biass[64 + tid]  = bk[tid];
        biass[128 + tid] = bv[tid];
    }
    for (int idx = tid; idx < 8192; idx += 256) {
        int cc = idx >> 7, j = idx & 127;
        float v = x[(size_t)(b * 64 + cc) * 4096 + l0 + j];
        *(__half*)(sm + 24576 + swz(j * 128 + cc * 2)) = __float2half(v);
    }
    __syncthreads();

    uint32_t a[4][4];
    {
        const int m = lane >> 3;
        #pragma unroll
        for (int kt = 0; kt < 4; kt++) {
            int row = wr + (lane & 7) + (m & 1) * 8;
            int ch  = kt * 2 + (m >> 1);
            ldsm_x4(a[kt][0], a[kt][1], a[kt][2], a[kt][3],
                    xsm + swz(row * 128 + ch * 16));
        }
    }

    const int krow = (lane & 7) + ((lane >> 4) & 1) * 8;
    const int kch  = (lane >> 3) & 1;

    float acc[3][8][4];
    #pragma unroll
    for (int m3 = 0; m3 < 3; m3++)
        #pragma unroll
        for (int nt = 0; nt < 8; nt++)
            #pragma unroll
            for (int e = 0; e < 4; e++) acc[m3][nt][e] = 0.f;

    #pragma unroll
    for (int m3 = 0; m3 < 3; m3++) {
        const uint32_t wb = wsm + m3 * 8192;
        #pragma unroll
        for (int kt = 0; kt < 4; kt++) {
            #pragma unroll
            for (int j = 0; j < 4; j++) {
                uint32_t b0, b1, b2, b3;
                int row = j * 16 + krow;
                int ch  = kt * 2 + kch;
                ldsm_x4(b0, b1, b2, b3, wb + swz(row * 128 + ch * 16));
                mma_h16_f32(acc[m3][2*j][0], acc[m3][2*j][1], acc[m3][2*j][2], acc[m3][2*j][3],
                            a[kt][0], a[kt][1], a[kt][2], a[kt][3], b0, b1);
                mma_h16_f32(acc[m3][2*j+1][0], acc[m3][2*j+1][1], acc[m3][2*j+1][2], acc[m3][2*j+1][3],
                            a[kt][0], a[kt][1], a[kt][2], a[kt][3], b2, b3);
            }
        }
    }

    const float fscale = 0.015625f * 1.4426950408889634f;  // (1/64)*log2(e)
    const int r0 = wr + (lane >> 2);
    #pragma unroll
    for (int nt = 0; nt < 8; nt++) {
        int c0 = nt * 8 + (lane & 3) * 2;
        float bQ0 = biass[c0],       bQ1 = biass[c0 + 1];
        float bK0 = biass[64 + c0],  bK1 = biass[64 + c0 + 1];
        float bV0 = biass[128 + c0], bV1 = biass[128 + c0 + 1];
        #pragma unroll
        for (int h = 0; h < 2; h++) {
            size_t go = ((size_t)b * 4096 + l0 + r0 + h * 8) * 64 + c0;
            *(uint32_t*)(g_Q + go) = packh((acc[0][nt][2*h] + bQ0) * fscale,
                                           (acc[0][nt][2*h+1] + bQ1) * fscale);
            *(uint32_t*)(g_K + go) = packh(acc[1][nt][2*h] + bK0,
                                           acc[1][nt][2*h+1] + bK1);
            *(uint32_t*)(g_V + go) = packh(acc[2][nt][2*h] + bV0,
                                           acc[2][nt][2*h+1] + bV1);
        }
    }
}

// ---------------------------------------------------------------------------
// Kernel B: FlashAttention, fp16 end-to-end with f16 accumulators.
// Br=128 (4 warps x 32 rows, 2 mtiles/warp), Bc=64 in two 32-key passes,
// 3-stage cp.async, 2 CTAs/SM desynchronized.
// The f16 D-register layout == A-fragment layout, so P = ex2.f16x2(S-regs)
// feeds PV directly with zero packing.
// out[b,c,l] = gamma * (softmax(Q K^T / 64) V)[l,c] + x[b,c,l]
// ---------------------------------------------------------------------------
// dynamic smem (65536 B):
//  main:     Q [128][128B] @0 (16KB) | K 3x8KB @16384 | V 3x8KB @40960
//  epilogue: Os [64][132] f32 @0 (33792 B) overlay
__global__ void __launch_bounds__(128, 2) attn_kernel(
    const float* __restrict__ x,
    const float* __restrict__ gamma,
    float* __restrict__ out)
{
    extern __shared__ __align__(16) unsigned char smem[];
    const int b    = blockIdx.x >> 5;
    const int q0   = (blockIdx.x & 31) * BR;
    const int tid  = threadIdx.x;
    const int lane = tid & 31;
    const int warp = tid >> 5;
    const int wr   = warp * 32;

    const uint32_t qs = smem_u32(smem);
    const uint32_t ks = qs + 16384;
    const uint32_t vs = qs + 40960;

    const __half* Qg = g_Q + ((size_t)b * L + q0) * C;
    const __half* Kg = g_K + (size_t)b * L * C;
    const __half* Vg = g_V + (size_t)b * L * C;

    // Prologue: group0 = Q + stage0, group1 = stage1
    for (int i = tid; i < 1024; i += 128) {
        int r = i >> 3, ck = i & 7;
        cp16(qs + swz(r * 128 + ck * 16), (const char*)Qg + r * 128 + ck * 16);
    }
    for (int i = tid; i < 512; i += 128) {
        int r = i >> 3, ck = i & 7;
        uint32_t so = swz(r * 128 + ck * 16);
        cp16(ks + so, (const char*)Kg + r * 128 + ck * 16);
        cp16(vs + so, (const char*)Vg + r * 128 + ck * 16);
    }
    cp_commit();
    {
        const char* K1 = (const char*)(Kg + (size_t)BC * C);
        const char* V1 = (const char*)(Vg + (size_t)BC * C);
        for (int i = tid; i < 512; i += 128) {
            int r = i >> 3, ck = i & 7;
            uint32_t so = swz(r * 128 + ck * 16);
            cp16(ks + 8192 + so, K1 + r * 128 + ck * 16);
            cp16(vs + 8192 + so, V1 + r * 128 + ck * 16);
        }
        cp_commit();
    }
    cp_wait<1>();          // Q + stage0 complete
    __syncthreads();

    // Q fragments: [mtile 0..1][ktile 0..3][4 regs]
    uint32_t qa[2][4][4];
    {
        const int m = lane >> 3;
        #pragma unroll
        for (int mt = 0; mt < 2; mt++)
            #pragma unroll
            for (int kt = 0; kt < 4; kt++) {
                int row = wr + mt * 16 + (lane & 7) + (m & 1) * 8;
                int ch  = kt * 2 + (m >> 1);
                ldsm_x4(qa[mt][kt][0], qa[mt][kt][1], qa[mt][kt][2], qa[mt][kt][3],
                        qs + swz(row * 128 + ch * 16));
            }
    }

    float lpart[4] = {0.f, 0.f, 0.f, 0.f};
    uint32_t o[2][8][2];   // f16x2 accumulators
    #pragma unroll
    for (int mt = 0; mt < 2; mt++)
        #pragma unroll
        for (int ct = 0; ct < 8; ct++) { o[mt][ct][0] = 0u; o[mt][ct][1] = 0u; }

    // Per-lane invariant address components
    const int krow = (lane & 7) + ((lane >> 4) & 1) * 8;   // + hp*32 + j*16
    const int kch  = (lane >> 3) & 1;                      // + kt*2
    const int vrow = (lane & 7) + ((lane >> 3) & 1) * 8;   // + hp*32 + kk*16
    const int vcb  = ((lane >> 4) & 1) * 16;               // + j*32 (bytes)

    for (int it = 0; it < NIT; it++) {
        // Prefetch stage it+2 into buffer (it+2)%3
        if (it + 2 < NIT) {
            int nb = (it + 2) % 3;
            const char* Kn = (const char*)(Kg + (size_t)(it + 2) * BC * C);
            const char* Vn = (const char*)(Vg + (size_t)(it + 2) * BC * C);
            for (int i = tid; i < 512; i += 128) {
                int r = i >> 3, ck = i & 7;
                uint32_t so = swz(r * 128 + ck * 16);
                cp16(ks + nb * 8192 + so, Kn + r * 128 + ck * 16);
                cp16(vs + nb * 8192 + so, Vn + r * 128 + ck * 16);
            }
            cp_commit();
        }

        const uint32_t kbase = ks + (it % 3) * 8192;
        const uint32_t vbase = vs + (it % 3) * 8192;

        // Two passes over 32-key halves
        #pragma unroll
        for (int hp = 0; hp < 2; hp++) {
            // S = Q K^T over 32 keys, f16 accumulate
            uint32_t s[2][4][2];
            #pragma unroll
            for (int mt = 0; mt < 2; mt++)
                #pragma unroll
                for (int nt = 0; nt < 4; nt++) { s[mt][nt][0] = 0u; s[mt][nt][1] = 0u; }

            #pragma unroll
            for (int kt = 0; kt < 4; kt++) {
                #pragma unroll
                for (int j = 0; j < 2; j++) {
                    uint32_t b0, b1, b2, b3;
                    int row = hp * 32 + j * 16 + krow;
                    int ch  = kt * 2 + kch;
                    ldsm_x4(b0, b1, b2, b3, kbase + swz(row * 128 + ch * 16));
                    #pragma unroll
                    for (int mt = 0; mt < 2; mt++) {
                        mma_h16(s[mt][2*j][0], s[mt][2*j][1],
                                qa[mt][kt][0], qa[mt][kt][1], qa[mt][kt][2], qa[mt][kt][3],
                                b0, b1);
                        mma_h16(s[mt][2*j+1][0], s[mt][2*j+1][1],
                                qa[mt][kt][0], qa[mt][kt][1], qa[mt][kt][2], qa[mt][kt][3],
                                b2, b3);
                    }
                }
            }

            // P = exp2(S) — S accumulator regs ARE the A-fragment layout.
            uint32_t pf[2][4][2];
            #pragma unroll
            for (int mt = 0; mt < 2; mt++) {
                uint32_t l2a = 0u, l2b = 0u;
                #pragma unroll
                for (int nt = 0; nt < 4; nt++) {
                    uint32_t u0 = ex2_h2(s[mt][nt][0]);
                    uint32_t u1 = ex2_h2(s[mt][nt][1]);
                    pf[mt][nt][0] = u0; pf[mt][nt][1] = u1;
                    l2a = hadd2u(l2a, u0);
                    l2b = hadd2u(l2b, u1);
                }
                float2 fa = h2_to_f2(l2a), fb = h2_to_f2(l2b);
                lpart[mt * 2]     += fa.x + fa.y;
                lpart[mt * 2 + 1] += fb.x + fb.y;
            }

            // O += P V over these 32 keys (all 64 channels), f16 accumulate
            #pragma unroll
            for (int kk = 0; kk < 2; kk++) {
                #pragma unroll
                for (int j = 0; j < 4; j++) {
                    uint32_t v0, v1, v2, v3;
                    int row = hp * 32 + kk * 16 + vrow;
                    ldsm_x4t(v0, v1, v2, v3, vbase + swz(row * 128 + j * 32 + vcb));
                    #pragma unroll
                    for (int mt = 0; mt < 2; mt++) {
                        mma_h16(o[mt][2*j][0], o[mt][2*j][1],
                                pf[mt][2*kk][0], pf[mt][2*kk][1],
                                pf[mt][2*kk+1][0], pf[mt][2*kk+1][1], v0, v1);
                        mma_h16(o[mt][2*j+1][0], o[mt][2*j+1][1],
                                pf[mt][2*kk][0], pf[mt][2*kk][1],
                                pf[mt][2*kk+1][0], pf[mt][2*kk+1][1], v2, v3);
                    }
                }
            }
        }

        if (it + 1 < NIT) {
            if (it + 2 < NIT) cp_wait<1>(); else cp_wait<0>();
            __syncthreads();
        }
    }

    // Row-sum reduction within quads (columns of a row live across lanes ^1,^2)
    #pragma unroll
    for (int h = 0; h < 4; h++) {
        lpart[h] += __shfl_xor_sync(0xffffffffu, lpart[h], 1);
        lpart[h] += __shfl_xor_sync(0xffffffffu, lpart[h], 2);
    }
    float inv[4];
    #pragma unroll
    for (int h = 0; h < 4; h++) inv[h] = fast_rcp(lpart[h]);

    // Epilogue: normalize, transpose through smem, fused residual write
    __syncthreads();
    float* Os = (float*)smem;   // [64][132]

    #pragma unroll
    for (int mt = 0; mt < 2; mt++)
        #pragma unroll
        for (int h = 0; h < 2; h++) {
            int row  = wr + mt * 16 + h * 8 + (lane >> 2);
            float iv = inv[mt * 2 + h];
            #pragma unroll
            for (int ct = 0; ct < 8; ct++) {
                int c0 = ct * 8 + 2 * (lane & 3);
                float2 f = h2_to_f2(o[mt][ct][h]);
                Os[c0 * 132 + row]       = f.x * iv;
                Os[(c0 + 1) * 132 + row] = f.y * iv;
            }
        }
    __syncthreads();

    const float gam = gamma[0];
    for (int idx = tid; idx < 64 * 128; idx += 128) {
        int c = idx >> 7, j = idx & 127;
        size_t gi = ((size_t)(b * 64 + c)) * 4096 + q0 + j;
        out[gi] = gam * Os[c * 132 + j] + x[gi];
    }
}

// ---------------------------------------------------------------------------
extern "C" void kernel_launch(void* const* d_in, const int* in_sizes, int n_in,
                              void* d_out, int out_size) {
    (void)in_sizes; (void)n_in; (void)out_size;
    const float* x     = (const float*)d_in[0];
    const float* Wq    = (const float*)d_in[1];
    const float* bq    = (const float*)d_in[2];
    const float* Wk    = (const float*)d_in[3];
    const float* bk    = (const float*)d_in[4];
    const float* Wv    = (const float*)d_in[5];
    const float* bv    = (const float*)d_in[6];
    const float* gamma = (const float*)d_in[7];
    float* out = (float*)d_out;

    cudaFuncSetAttribute(attn_kernel, cudaFuncAttributeMaxDynamicSharedMemorySize, 65536);

    qkv_kernel<<<NB * 32, 256>>>(x, Wq, bq, Wk, bk, Wv, bv);
    attn_kernel<<<NB * (L / BR), 128, 65536>>>(x, gamma, out);
}